// round 13
// baseline (speedup 1.0000x reference)
#include <cuda_runtime.h>
#include <math.h>

// ---------------- problem constants ----------------
#define NB    32
#define NCOL  160
#define NOUT  10
#define OFF_DIST 320
#define OFF_PROB 5440
#define OFF_LOSS 10560

#define NBLK  444                 // 148 SMs * 3 blocks = one wave
#define NTICK 544                 // 32*(3+4+5+5) passes (16-window items)

// smem layout (words)
#define SXSTR 532                 // mult of 4 (LDS.128 aligned); 532%32=20 -> conflict-free
#define SXW   (8*SXSTR)           // 4256
#define SWW   260                 // mult of 4, nc*260%32=nc*4 -> conflict-free per 8-lane phase
#define SRED  (SXW + 40*SWW)      // 14656: sden[40] + sq[40]
#define SM_WORDS (SRED + 80)      // 14736
#define SM_BYTES (SM_WORDS*4)     // 58944 B -> 3 blocks/SM

__device__ unsigned g_d[NB*NCOL] = {};
__device__ unsigned g_q[NB*NCOL] = {};
__device__ unsigned g_tick = 0;
__device__ unsigned g_ctr  = 0;

__device__ __forceinline__ unsigned fenc(float f){unsigned u=__float_as_uint(f);return (u&0x80000000u)?~u:(u|0x80000000u);}
__device__ __forceinline__ float fdec(unsigned e){unsigned u=(e&0x80000000u)?(e&0x7fffffffu):~e;return __uint_as_float(u);}
__device__ __forceinline__ unsigned ienc(float f){ return ~fenc(f); }   // max(ienc) = min(f); 0 sentinel
__device__ __forceinline__ float idec(unsigned e){ return fdec(~e); }

// ring rotations (compile-time renaming, no MOVs)
#define R0  x0,x1,x2,x3,x4,x5,x6,x7,x8,x9,x10,x11,x12,x13,x14,x15
#define R1  x1,x2,x3,x4,x5,x6,x7,x8,x9,x10,x11,x12,x13,x14,x15,x0
#define R2  x2,x3,x4,x5,x6,x7,x8,x9,x10,x11,x12,x13,x14,x15,x0,x1
#define R3  x3,x4,x5,x6,x7,x8,x9,x10,x11,x12,x13,x14,x15,x0,x1,x2
#define R4  x4,x5,x6,x7,x8,x9,x10,x11,x12,x13,x14,x15,x0,x1,x2,x3
#define R5  x5,x6,x7,x8,x9,x10,x11,x12,x13,x14,x15,x0,x1,x2,x3,x4
#define R6  x6,x7,x8,x9,x10,x11,x12,x13,x14,x15,x0,x1,x2,x3,x4,x5
#define R7  x7,x8,x9,x10,x11,x12,x13,x14,x15,x0,x1,x2,x3,x4,x5,x6
#define R8  x8,x9,x10,x11,x12,x13,x14,x15,x0,x1,x2,x3,x4,x5,x6,x7
#define R9  x9,x10,x11,x12,x13,x14,x15,x0,x1,x2,x3,x4,x5,x6,x7,x8
#define R10 x10,x11,x12,x13,x14,x15,x0,x1,x2,x3,x4,x5,x6,x7,x8,x9
#define R11 x11,x12,x13,x14,x15,x0,x1,x2,x3,x4,x5,x6,x7,x8,x9,x10
#define R12 x12,x13,x14,x15,x0,x1,x2,x3,x4,x5,x6,x7,x8,x9,x10,x11
#define R13 x13,x14,x15,x0,x1,x2,x3,x4,x5,x6,x7,x8,x9,x10,x11,x12
#define R14 x14,x15,x0,x1,x2,x3,x4,x5,x6,x7,x8,x9,x10,x11,x12,x13
#define R15 x15,x0,x1,x2,x3,x4,x5,x6,x7,x8,x9,x10,x11,x12,x13,x14

// 18-arg worker: 16 window-accumulates + 1 ring refill (oldest slot a0)
#define STEP2(W,JJ,a0,a1,a2,a3,a4,a5,a6,a7,a8,a9,aA,aB,aC,aD,aE,aF) do { \
    float w_ = (W); \
    acc0  += fabsf(a0 - w_);  acc1  += fabsf(a1 - w_); \
    acc2  += fabsf(a2 - w_);  acc3  += fabsf(a3 - w_); \
    acc4  += fabsf(a4 - w_);  acc5  += fabsf(a5 - w_); \
    acc6  += fabsf(a6 - w_);  acc7  += fabsf(a7 - w_); \
    acc8  += fabsf(a8 - w_);  acc9  += fabsf(a9 - w_); \
    acc10 += fabsf(aA - w_);  acc11 += fabsf(aB - w_); \
    acc12 += fabsf(aC - w_);  acc13 += fabsf(aD - w_); \
    acc14 += fabsf(aE - w_);  acc15 += fabsf(aF - w_); \
    a0 = xr[(JJ) + 16]; \
} while (0)
#define STEP(W, JJ, RING) STEP2(W, JJ, RING)

#define FIN(K, A) do { \
    int mm = 16*tl + (K); \
    if (mm < M) { \
        float d_ = (A) * INVL * prv[K]; \
        dmin = fminf(dmin, d_); \
        qmin = fminf(qmin, fabsf(d_)); \
    } \
} while (0)

// ---------------- one item = 16 consecutive windows ----------------
template<int L, int M>
__device__ __forceinline__ void item1(const float* __restrict__ sx, const float* __restrict__ sw,
                                      const float* __restrict__ pcm,
                                      unsigned* __restrict__ sden, unsigned* __restrict__ sq, int idx)
{
    constexpr int MAIN = L & ~15;
    constexpr int REM  = L & 15;
    constexpr float INVL = 1.0f/(float)L;

    int tl = idx / 40;
    int nc = idx - tl*40;
    int c  = nc & 7;
    const float* xr = sx + c*SXSTR + 16*tl;
    const float* wr = sw + nc*SWW;

    // pcm prefetch (latency hidden behind the main loop)
    float prv[16];
#pragma unroll
    for (int k = 0; k < 16; k++) {
        int mm = 16*tl + k;
        prv[k] = __ldg(&pcm[c*M + (mm < M ? mm : M-1)]);
    }

    // x prologue: 4x LDS.128 (aligned, conflict-free)
    float4 xa = *(const float4*)(xr);
    float4 xb = *(const float4*)(xr + 4);
    float4 xc = *(const float4*)(xr + 8);
    float4 xd = *(const float4*)(xr + 12);
    float x0=xa.x,x1=xa.y,x2=xa.z,x3=xa.w, x4=xb.x,x5=xb.y,x6=xb.z,x7=xb.w;
    float x8=xc.x,x9=xc.y,x10=xc.z,x11=xc.w, x12=xd.x,x13=xd.y,x14=xd.z,x15=xd.w;
    float acc0=0.f,acc1=0.f,acc2=0.f,acc3=0.f,acc4=0.f,acc5=0.f,acc6=0.f,acc7=0.f;
    float acc8=0.f,acc9=0.f,acc10=0.f,acc11=0.f,acc12=0.f,acc13=0.f,acc14=0.f,acc15=0.f;

    // w double-buffered: load next float4 before consuming current
    float4 wA = *(const float4*)(wr);
    for (int j = 0; j < MAIN; j += 16) {
        float4 wB = *(const float4*)(wr + j + 4);
        STEP(wA.x, j+0,  R0);  STEP(wA.y, j+1,  R1);  STEP(wA.z, j+2,  R2);  STEP(wA.w, j+3,  R3);
        float4 wC = *(const float4*)(wr + j + 8);
        STEP(wB.x, j+4,  R4);  STEP(wB.y, j+5,  R5);  STEP(wB.z, j+6,  R6);  STEP(wB.w, j+7,  R7);
        float4 wD = *(const float4*)(wr + j + 12);
        STEP(wC.x, j+8,  R8);  STEP(wC.y, j+9,  R9);  STEP(wC.z, j+10, R10); STEP(wC.w, j+11, R11);
        wA = *(const float4*)(wr + j + 16);   // safe: SWW=260 >= L+4
        STEP(wD.x, j+12, R12); STEP(wD.y, j+13, R13); STEP(wD.z, j+14, R14); STEP(wD.w, j+15, R15);
    }
    // tail (REM steps); wA already holds wr[MAIN..MAIN+3]
    if (REM > 0) {
        STEP(wA.x, MAIN+0, R0);
        if (REM > 1) STEP(wA.y, MAIN+1, R1);
        if (REM > 2) STEP(wA.z, MAIN+2, R2);
        if (REM > 3) STEP(wA.w, MAIN+3, R3);
    }
    if (REM > 4) {
        float4 v = *(const float4*)(wr + MAIN + 4);
        STEP(v.x, MAIN+4, R4);
        if (REM > 5) STEP(v.y, MAIN+5, R5);
        if (REM > 6) STEP(v.z, MAIN+6, R6);
        if (REM > 7) STEP(v.w, MAIN+7, R7);
    }
    if (REM > 8) {
        float4 v = *(const float4*)(wr + MAIN + 8);
        STEP(v.x, MAIN+8, R8);
        if (REM > 9)  STEP(v.y, MAIN+9,  R9);
        if (REM > 10) STEP(v.z, MAIN+10, R10);
        if (REM > 11) STEP(v.w, MAIN+11, R11);
    }
    if (REM > 12) {
        float4 v = *(const float4*)(wr + MAIN + 12);
        STEP(v.x, MAIN+12, R12);
        if (REM > 13) STEP(v.y, MAIN+13, R13);
        if (REM > 14) STEP(v.z, MAIN+14, R14);
    }

    float dmin = 3.4e38f, qmin = 3.4e38f;
    FIN(0,acc0);   FIN(1,acc1);   FIN(2,acc2);   FIN(3,acc3);
    FIN(4,acc4);   FIN(5,acc5);   FIN(6,acc6);   FIN(7,acc7);
    FIN(8,acc8);   FIN(9,acc9);   FIN(10,acc10); FIN(11,acc11);
    FIN(12,acc12); FIN(13,acc13); FIN(14,acc14); FIN(15,acc15);

    atomicMax(&sden[nc], ienc(dmin));   // smem atomics (spread addresses)
    atomicMax(&sq[nc],   ienc(qmin));
}

// compile-time-L weight staging (constant division)
template<int L>
__device__ __forceinline__ void stage_w(float* __restrict__ sw, const float* __restrict__ wp, int tid) {
    for (int i2 = tid; i2 < 40*L; i2 += 256) {
        int r = i2 / L, j = i2 - r*L;     // L constexpr -> mul/shift
        sw[r*SWW + j] = wp[i2];
    }
}

// ---------------- fused persistent kernel ----------------
__global__ __launch_bounds__(256, 3)
void k_all(const float* __restrict__ x,
           const float* __restrict__ w0, const float* __restrict__ w1,
           const float* __restrict__ w2, const float* __restrict__ w3,
           const float* __restrict__ p0, const float* __restrict__ p1,
           const float* __restrict__ p2, const float* __restrict__ p3,
           const float* __restrict__ Wout, float* __restrict__ out)
{
    extern __shared__ float sm[];
    float* sx = sm;
    float* sw = sm + SXW;
    unsigned* sden = (unsigned*)(sm + SRED);   // [40]
    unsigned* sq   = sden + 40;                // [40]
    __shared__ int sh_t;
    __shared__ unsigned s_old;

    int tid = threadIdx.x;
    int bx = blockIdx.x;

    if (tid < 80) sden[tid] = 0u;   // init sden+sq (visible at first restage sync)

    // ---- block 0: losses first (touch only sm[0..1792), below SRED) ----
    if (bx == 0) {
        float* sf   = sm;            // [640]
        float* sr   = sm + 640;      // [640]
        float* sval = sm + 1280;     // [256]
        float* sreg = sm + 1536;     // [256]

        float reg = 0.f;
        for (int i = tid; i < NOUT*NCOL; i += 256) reg += fabsf(Wout[i]);
        sreg[tid] = reg;

        const int Ls[4] = {52, 103, 154, 256};
        const float* wls[4] = {w0, w1, w2, w3};
        const signed char I1[10] = {0,0,0,0,1,1,1,2,2,3};
        const signed char J1[10] = {1,2,3,4,2,3,4,3,4,4};

        for (int u = tid; u < 640; u += 256) {
            int pp = u >> 1, h = u & 1;
            int s = pp / 80; int r = pp - s*80;
            int c = r / 10; int pr = r - c*10;
            int i = I1[pr], j = J1[pr];
            int L = Ls[s];
            const float* wa = wls[s] + (i*8 + c)*L;
            const float* wb = wls[s] + (j*8 + c)*L;
            int k0 = h ? (L >> 1) : 0;
            int k1 = h ? L : (L >> 1);
            float af = 0.f, ar = 0.f;
#pragma unroll 8
            for (int k = k0; k < k1; k++) {
                float t = wa[k] - wb[k];
                float df = t + 1e-6f, dr = 1e-6f - t;
                af += df*df; ar += dr*dr;
            }
            sf[u] = af; sr[u] = ar;
        }
        __syncthreads();
        float val = 0.f;
        for (int pp = tid; pp < 320; pp += 256) {
            float ssf = sf[2*pp] + sf[2*pp + 1];
            float ssr = sr[2*pp] + sr[2*pp + 1];
            val += (expf(-sqrtf(ssf)) + expf(-sqrtf(ssr))) * (1.f/200.f);
        }
        sval[tid] = val;
        __syncthreads();
        for (int off = 128; off; off >>= 1) {
            if (tid < off) { sval[tid] += sval[tid+off]; sreg[tid] += sreg[tid+off]; }
            __syncthreads();
        }
        if (tid == 0) out[OFF_LOSS] = 0.1f*(sreg[0]/1600.f) + 0.1f*sval[0];
        __syncthreads();
    }

    const float* wps[4] = {w0, w1, w2, w3};
    const float* pps[4] = {p0, p1, p2, p3};

    int cur_b = -1, cur_s = -1;
    // static first ticket, expensive-first; loss block takes the cheapest static ticket
    int t = (bx == 0) ? (NBLK - 1) : (bx - 1);
    for (;;) {
        // ticket -> (set, batch, pass). Order: set3(96), set2(128), set1(160), set0(160)
        int s, b, pass;
        if (t < 96)       { s = 3; b = t/3;            pass = t - b*3; }
        else if (t < 224) { int u = t-96;  s = 2; b = u/4; pass = u - b*4; }
        else if (t < 384) { int u = t-224; s = 1; b = u/9 ? 0 : 0, b = u/5; pass = u - b*5; }
        else              { int u = t-384; s = 0; b = u/5; pass = u - b*5; }

        if (b != cur_b || s != cur_s) {
            __syncthreads();          // prior readers done before restage
            if (b != cur_b) {
                int wp_ = tid >> 5, lane = tid & 31;
                const float* row = x + (b*8 + wp_)*512;
                float v[16]; float sv = 0.f;
#pragma unroll
                for (int i = 0; i < 16; i++) { v[i] = row[lane + 32*i]; sv += v[i]; }
#pragma unroll
                for (int o = 16; o; o >>= 1) sv += __shfl_xor_sync(0xffffffffu, sv, o);
                float mu = sv * (1.f/512.f);
                float qq = 0.f;
#pragma unroll
                for (int i = 0; i < 16; i++) { float d = v[i]-mu; qq += d*d; }
#pragma unroll
                for (int o = 16; o; o >>= 1) qq += __shfl_xor_sync(0xffffffffu, qq, o);
                float sc = 1.f / (sqrtf(qq * (1.f/511.f)) + 1e-8f);
                float* orow = sx + wp_*SXSTR;
#pragma unroll
                for (int i = 0; i < 16; i++) orow[lane + 32*i] = (v[i]-mu)*sc;
                if (lane < SXSTR - 512) orow[512 + lane] = 0.f;
                cur_b = b;
            }
            if (s != cur_s) {
                switch (s) {
                    case 0:  stage_w< 52>(sw, wps[0], tid); break;
                    case 1:  stage_w<103>(sw, wps[1], tid); break;
                    case 2:  stage_w<154>(sw, wps[2], tid); break;
                    default: stage_w<256>(sw, wps[3], tid); break;
                }
                cur_s = s;
            }
            __syncthreads();
        }

        int i = pass*256 + tid;
        switch (s) {
            case 0:  if (i < 1160) item1< 52,461>(sx, sw, pps[0], sden, sq, i); break;
            case 1:  if (i < 1040) item1<103,410>(sx, sw, pps[1], sden, sq, i); break;
            case 2:  if (i <  920) item1<154,359>(sx, sw, pps[2], sden, sq, i); break;
            default: if (i <  680) item1<256,257>(sx, sw, pps[3], sden, sq, i); break;
        }
        __syncthreads();              // all items done
        // flush this ticket's partials to global, reset for next ticket
        if (tid < 40) {
            int gi = b*NCOL + s*40 + tid;
            unsigned dv = sden[tid], qv = sq[tid];
            if (dv) atomicMax(&g_d[gi], dv);
            if (qv) atomicMax(&g_q[gi], qv);
            sden[tid] = 0u; sq[tid] = 0u;
        }
        if (tid == 0) sh_t = (int)(atomicAdd(&g_tick, 1u) + NBLK);
        __syncthreads();
        t = sh_t;
        if (t >= NTICK) break;
    }

    // ---- completion counter: last block finalizes ----
    __threadfence();
    __syncthreads();
    if (tid == 0) s_old = atomicAdd(&g_ctr, 1u);
    __syncthreads();
    if (s_old != NBLK - 1) return;

    __threadfence();
    float* sprob = sm;              // [5120]
    float* swout = sm + 5120;       // [1600]
    for (int i = tid; i < NB*NCOL; i += 256) {
        unsigned de = atomicMax(&g_d[i], 0u);   // L2-coherent read
        unsigned qe = atomicMax(&g_q[i], 0u);
        g_d[i] = 0u; g_q[i] = 0u;               // reset for next replay
        float qv = idec(qe);
        float p = expf(-qv*qv);
        out[OFF_DIST + i] = idec(de);
        out[OFF_PROB + i] = p;
        sprob[i] = p;
    }
    for (int i = tid; i < NOUT*NCOL; i += 256) swout[i] = Wout[i];
    __syncthreads();
    for (int tt = tid; tt < NB*NOUT; tt += 256) {
        int bb = tt / NOUT, o = tt - bb*NOUT;
        const float* pr = sprob + bb*NCOL;
        const float* wr = swout + o*NCOL;
        float acc = 0.f;
#pragma unroll 8
        for (int j = 0; j < NCOL; j++) acc += pr[j]*wr[j];
        out[bb*NOUT + o] = acc;
    }
    if (tid == 0) { g_tick = 0u; g_ctr = 0u; }
}

// ---------------- launch ----------------
extern "C" void kernel_launch(void* const* d_in, const int* in_sizes, int n_in,
                              void* d_out, int out_size) {
    const float* x = nullptr;
    const float* w[4] = {nullptr,nullptr,nullptr,nullptr};
    const float* pcm[4] = {nullptr,nullptr,nullptr,nullptr};
    const float* Wout = nullptr;
    for (int i = 0; i < n_in; i++) {
        switch (in_sizes[i]) {
            case 131072: x = (const float*)d_in[i]; break;
            case 2080:  w[0] = (const float*)d_in[i]; break;
            case 4120:  w[1] = (const float*)d_in[i]; break;
            case 6160:  w[2] = (const float*)d_in[i]; break;
            case 10240: w[3] = (const float*)d_in[i]; break;
            case 3688:  pcm[0] = (const float*)d_in[i]; break;
            case 3280:  pcm[1] = (const float*)d_in[i]; break;
            case 2872:  pcm[2] = (const float*)d_in[i]; break;
            case 2056:  pcm[3] = (const float*)d_in[i]; break;
            case 1600:  Wout = (const float*)d_in[i]; break;
            default: break;
        }
    }
    float* out = (float*)d_out;

    cudaFuncSetAttribute(k_all, cudaFuncAttributeMaxDynamicSharedMemorySize, SM_BYTES);

    k_all<<<NBLK, 256, SM_BYTES>>>(x, w[0], w[1], w[2], w[3],
                                   pcm[0], pcm[1], pcm[2], pcm[3], Wout, out);
    (void)out_size;
}

// round 14
// speedup vs baseline: 1.0498x; 1.0498x over previous
#include <cuda_runtime.h>
#include <math.h>

// ---------------- problem constants ----------------
#define NB    32
#define NCOL  160
#define NOUT  10
#define OFF_DIST 320
#define OFF_PROB 5440
#define OFF_LOSS 10560

#define NT    512                 // threads per block
#define NBLK  296                 // 148 SMs * 2 blocks = one wave
#define NTICK 320                 // 32*(3+3+2+2) passes (512-item passes)

// smem layout (words)
#define SXSTR 532                 // mult of 4 (LDS.128 aligned); 532%32=20 -> conflict-free
#define SXW   (8*SXSTR)           // 4256
#define SWW   260                 // mult of 4; nc*260%32=nc*4 -> conflict-free per 8-lane phase
#define SRED  (SXW + 40*SWW)      // 14656: sden[40] + sq[40]
#define SM_WORDS (SRED + 80)      // 14736
#define SM_BYTES (SM_WORDS*4)     // 58944 B -> 2 blocks/SM at 512 threads

__device__ unsigned g_d[NB*NCOL] = {};
__device__ unsigned g_q[NB*NCOL] = {};
__device__ unsigned g_tick = 0;
__device__ unsigned g_ctr  = 0;

__device__ __forceinline__ unsigned fenc(float f){unsigned u=__float_as_uint(f);return (u&0x80000000u)?~u:(u|0x80000000u);}
__device__ __forceinline__ float fdec(unsigned e){unsigned u=(e&0x80000000u)?(e&0x7fffffffu):~e;return __uint_as_float(u);}
__device__ __forceinline__ unsigned ienc(float f){ return ~fenc(f); }   // max(ienc) = min(f); 0 sentinel
__device__ __forceinline__ float idec(unsigned e){ return fdec(~e); }

// ring rotations (compile-time renaming, no MOVs)
#define R0  x0,x1,x2,x3,x4,x5,x6,x7,x8,x9,x10,x11,x12,x13,x14,x15
#define R1  x1,x2,x3,x4,x5,x6,x7,x8,x9,x10,x11,x12,x13,x14,x15,x0
#define R2  x2,x3,x4,x5,x6,x7,x8,x9,x10,x11,x12,x13,x14,x15,x0,x1
#define R3  x3,x4,x5,x6,x7,x8,x9,x10,x11,x12,x13,x14,x15,x0,x1,x2
#define R4  x4,x5,x6,x7,x8,x9,x10,x11,x12,x13,x14,x15,x0,x1,x2,x3
#define R5  x5,x6,x7,x8,x9,x10,x11,x12,x13,x14,x15,x0,x1,x2,x3,x4
#define R6  x6,x7,x8,x9,x10,x11,x12,x13,x14,x15,x0,x1,x2,x3,x4,x5
#define R7  x7,x8,x9,x10,x11,x12,x13,x14,x15,x0,x1,x2,x3,x4,x5,x6
#define R8  x8,x9,x10,x11,x12,x13,x14,x15,x0,x1,x2,x3,x4,x5,x6,x7
#define R9  x9,x10,x11,x12,x13,x14,x15,x0,x1,x2,x3,x4,x5,x6,x7,x8
#define R10 x10,x11,x12,x13,x14,x15,x0,x1,x2,x3,x4,x5,x6,x7,x8,x9
#define R11 x11,x12,x13,x14,x15,x0,x1,x2,x3,x4,x5,x6,x7,x8,x9,x10
#define R12 x12,x13,x14,x15,x0,x1,x2,x3,x4,x5,x6,x7,x8,x9,x10,x11
#define R13 x13,x14,x15,x0,x1,x2,x3,x4,x5,x6,x7,x8,x9,x10,x11,x12
#define R14 x14,x15,x0,x1,x2,x3,x4,x5,x6,x7,x8,x9,x10,x11,x12,x13
#define R15 x15,x0,x1,x2,x3,x4,x5,x6,x7,x8,x9,x10,x11,x12,x13,x14

// 18-arg worker: 16 window-accumulates + 1 ring refill (oldest slot a0)
#define STEP2(W,JJ,a0,a1,a2,a3,a4,a5,a6,a7,a8,a9,aA,aB,aC,aD,aE,aF) do { \
    float w_ = (W); \
    acc0  += fabsf(a0 - w_);  acc1  += fabsf(a1 - w_); \
    acc2  += fabsf(a2 - w_);  acc3  += fabsf(a3 - w_); \
    acc4  += fabsf(a4 - w_);  acc5  += fabsf(a5 - w_); \
    acc6  += fabsf(a6 - w_);  acc7  += fabsf(a7 - w_); \
    acc8  += fabsf(a8 - w_);  acc9  += fabsf(a9 - w_); \
    acc10 += fabsf(aA - w_);  acc11 += fabsf(aB - w_); \
    acc12 += fabsf(aC - w_);  acc13 += fabsf(aD - w_); \
    acc14 += fabsf(aE - w_);  acc15 += fabsf(aF - w_); \
    a0 = xr[(JJ) + 16]; \
} while (0)
#define STEP(W, JJ, RING) STEP2(W, JJ, RING)

#define FIN(K, A) do { \
    int mm = 16*tl + (K); \
    if (mm < M) { \
        float d_ = (A) * INVL * __ldg(&pr[mm]); \
        dmin = fminf(dmin, d_); \
        qmin = fminf(qmin, fabsf(d_)); \
    } \
} while (0)

// ---------------- one item = 16 consecutive windows ----------------
template<int L, int M>
__device__ __forceinline__ void item1(const float* __restrict__ sx, const float* __restrict__ sw,
                                      const float* __restrict__ pcm,
                                      unsigned* __restrict__ sden, unsigned* __restrict__ sq, int idx)
{
    constexpr int MAIN = L & ~15;
    constexpr int REM  = L & 15;
    constexpr float INVL = 1.0f/(float)L;

    int tl = idx / 40;
    int nc = idx - tl*40;
    int c  = nc & 7;
    const float* xr = sx + c*SXSTR + 16*tl;
    const float* wr = sw + nc*SWW;

    // x prologue: 4x LDS.128 (aligned, conflict-free)
    float4 xa = *(const float4*)(xr);
    float4 xb = *(const float4*)(xr + 4);
    float4 xc = *(const float4*)(xr + 8);
    float4 xd = *(const float4*)(xr + 12);
    float x0=xa.x,x1=xa.y,x2=xa.z,x3=xa.w, x4=xb.x,x5=xb.y,x6=xb.z,x7=xb.w;
    float x8=xc.x,x9=xc.y,x10=xc.z,x11=xc.w, x12=xd.x,x13=xd.y,x14=xd.z,x15=xd.w;
    float acc0=0.f,acc1=0.f,acc2=0.f,acc3=0.f,acc4=0.f,acc5=0.f,acc6=0.f,acc7=0.f;
    float acc8=0.f,acc9=0.f,acc10=0.f,acc11=0.f,acc12=0.f,acc13=0.f,acc14=0.f,acc15=0.f;

    // w double-buffered: load next float4 before consuming current
    float4 wA = *(const float4*)(wr);
    for (int j = 0; j < MAIN; j += 16) {
        float4 wB = *(const float4*)(wr + j + 4);
        STEP(wA.x, j+0,  R0);  STEP(wA.y, j+1,  R1);  STEP(wA.z, j+2,  R2);  STEP(wA.w, j+3,  R3);
        float4 wC = *(const float4*)(wr + j + 8);
        STEP(wB.x, j+4,  R4);  STEP(wB.y, j+5,  R5);  STEP(wB.z, j+6,  R6);  STEP(wB.w, j+7,  R7);
        float4 wD = *(const float4*)(wr + j + 12);
        STEP(wC.x, j+8,  R8);  STEP(wC.y, j+9,  R9);  STEP(wC.z, j+10, R10); STEP(wC.w, j+11, R11);
        wA = *(const float4*)(wr + j + 16);   // safe: SWW=260 >= L+4
        STEP(wD.x, j+12, R12); STEP(wD.y, j+13, R13); STEP(wD.z, j+14, R14); STEP(wD.w, j+15, R15);
    }
    // tail (REM steps); wA already holds wr[MAIN..MAIN+3]
    if (REM > 0) {
        STEP(wA.x, MAIN+0, R0);
        if (REM > 1) STEP(wA.y, MAIN+1, R1);
        if (REM > 2) STEP(wA.z, MAIN+2, R2);
        if (REM > 3) STEP(wA.w, MAIN+3, R3);
    }
    if (REM > 4) {
        float4 v = *(const float4*)(wr + MAIN + 4);
        STEP(v.x, MAIN+4, R4);
        if (REM > 5) STEP(v.y, MAIN+5, R5);
        if (REM > 6) STEP(v.z, MAIN+6, R6);
        if (REM > 7) STEP(v.w, MAIN+7, R7);
    }
    if (REM > 8) {
        float4 v = *(const float4*)(wr + MAIN + 8);
        STEP(v.x, MAIN+8, R8);
        if (REM > 9)  STEP(v.y, MAIN+9,  R9);
        if (REM > 10) STEP(v.z, MAIN+10, R10);
        if (REM > 11) STEP(v.w, MAIN+11, R11);
    }
    if (REM > 12) {
        float4 v = *(const float4*)(wr + MAIN + 12);
        STEP(v.x, MAIN+12, R12);
        if (REM > 13) STEP(v.y, MAIN+13, R13);
        if (REM > 14) STEP(v.z, MAIN+14, R14);
    }

    const float* pr = pcm + c*M;
    float dmin = 3.4e38f, qmin = 3.4e38f;
    FIN(0,acc0);   FIN(1,acc1);   FIN(2,acc2);   FIN(3,acc3);
    FIN(4,acc4);   FIN(5,acc5);   FIN(6,acc6);   FIN(7,acc7);
    FIN(8,acc8);   FIN(9,acc9);   FIN(10,acc10); FIN(11,acc11);
    FIN(12,acc12); FIN(13,acc13); FIN(14,acc14); FIN(15,acc15);

    atomicMax(&sden[nc], ienc(dmin));   // smem atomics (spread addresses)
    atomicMax(&sq[nc],   ienc(qmin));
}

// compile-time-L weight staging (constant division)
template<int L>
__device__ __forceinline__ void stage_w(float* __restrict__ sw, const float* __restrict__ wp, int tid) {
    for (int i2 = tid; i2 < 40*L; i2 += NT) {
        int r = i2 / L, j = i2 - r*L;     // L constexpr -> mul/shift
        sw[r*SWW + j] = wp[i2];
    }
}

// ---------------- fused persistent kernel ----------------
__global__ __launch_bounds__(NT, 2)
void k_all(const float* __restrict__ x,
           const float* __restrict__ w0, const float* __restrict__ w1,
           const float* __restrict__ w2, const float* __restrict__ w3,
           const float* __restrict__ p0, const float* __restrict__ p1,
           const float* __restrict__ p2, const float* __restrict__ p3,
           const float* __restrict__ Wout, float* __restrict__ out)
{
    extern __shared__ float sm[];
    float* sx = sm;
    float* sw = sm + SXW;
    unsigned* sden = (unsigned*)(sm + SRED);   // [40]
    unsigned* sq   = sden + 40;                // [40]
    __shared__ int sh_t;
    __shared__ unsigned s_old;

    int tid = threadIdx.x;
    int bx = blockIdx.x;

    if (tid < 80) sden[tid] = 0u;   // init sden+sq (region above loss scratch)

    // ---- block 0: losses first (touch only sm[0..1792), below SRED) ----
    if (bx == 0) {
        float* sf   = sm;            // [640]
        float* sr   = sm + 640;      // [640]
        float* sval = sm + 1280;     // [512]
        float* sreg = sm + 1792 + 128; // [512] at sm[1920..2432)

        float reg = 0.f;
        for (int i = tid; i < NOUT*NCOL; i += NT) reg += fabsf(Wout[i]);
        sreg[tid] = reg;

        const int Ls[4] = {52, 103, 154, 256};
        const float* wls[4] = {w0, w1, w2, w3};
        const signed char I1[10] = {0,0,0,0,1,1,1,2,2,3};
        const signed char J1[10] = {1,2,3,4,2,3,4,3,4,4};

        for (int u = tid; u < 640; u += NT) {
            int pp = u >> 1, h = u & 1;
            int s = pp / 80; int r = pp - s*80;
            int c = r / 10; int pr = r - c*10;
            int i = I1[pr], j = J1[pr];
            int L = Ls[s];
            const float* wa = wls[s] + (i*8 + c)*L;
            const float* wb = wls[s] + (j*8 + c)*L;
            int k0 = h ? (L >> 1) : 0;
            int k1 = h ? L : (L >> 1);
            float af = 0.f, ar = 0.f;
#pragma unroll 8
            for (int k = k0; k < k1; k++) {
                float t = wa[k] - wb[k];
                float df = t + 1e-6f, dr = 1e-6f - t;
                af += df*df; ar += dr*dr;
            }
            sf[u] = af; sr[u] = ar;
        }
        __syncthreads();
        float val = 0.f;
        for (int pp = tid; pp < 320; pp += NT) {
            float ssf = sf[2*pp] + sf[2*pp + 1];
            float ssr = sr[2*pp] + sr[2*pp + 1];
            val += (expf(-sqrtf(ssf)) + expf(-sqrtf(ssr))) * (1.f/200.f);
        }
        sval[tid] = val;
        __syncthreads();
        for (int off = 256; off; off >>= 1) {
            if (tid < off) { sval[tid] += sval[tid+off]; sreg[tid] += sreg[tid+off]; }
            __syncthreads();
        }
        if (tid == 0) out[OFF_LOSS] = 0.1f*(sreg[0]/1600.f) + 0.1f*sval[0];
        __syncthreads();
    }

    const float* wps[4] = {w0, w1, w2, w3};
    const float* pps[4] = {p0, p1, p2, p3};

    int cur_b = -1, cur_s = -1;
    // static first ticket, expensive-first; loss block takes the cheapest static ticket
    int t = (bx == 0) ? (NBLK - 1) : (bx - 1);
    for (;;) {
        // ticket -> (set, batch, pass). Order: set3(64), set2(64), set1(96), set0(96)
        int s, b, pass;
        if (t < 64)       { s = 3; b = t >> 1;            pass = t & 1; }
        else if (t < 128) { int u = t-64;  s = 2; b = u >> 1; pass = u & 1; }
        else if (t < 224) { int u = t-128; s = 1; b = u/3; pass = u - b*3; }
        else              { int u = t-224; s = 0; b = u/3; pass = u - b*3; }

        if (b != cur_b || s != cur_s) {
            __syncthreads();          // prior readers done before restage
            if (b != cur_b) {
                int wp_ = tid >> 5, lane = tid & 31;
                if (wp_ < 8) {
                    const float* row = x + (b*8 + wp_)*512;
                    float v[16]; float sv = 0.f;
#pragma unroll
                    for (int i = 0; i < 16; i++) { v[i] = row[lane + 32*i]; sv += v[i]; }
#pragma unroll
                    for (int o = 16; o; o >>= 1) sv += __shfl_xor_sync(0xffffffffu, sv, o);
                    float mu = sv * (1.f/512.f);
                    float qq = 0.f;
#pragma unroll
                    for (int i = 0; i < 16; i++) { float d = v[i]-mu; qq += d*d; }
#pragma unroll
                    for (int o = 16; o; o >>= 1) qq += __shfl_xor_sync(0xffffffffu, qq, o);
                    float sc = 1.f / (sqrtf(qq * (1.f/511.f)) + 1e-8f);
                    float* orow = sx + wp_*SXSTR;
#pragma unroll
                    for (int i = 0; i < 16; i++) orow[lane + 32*i] = (v[i]-mu)*sc;
                    if (lane < SXSTR - 512) orow[512 + lane] = 0.f;
                }
                cur_b = b;
            }
            if (s != cur_s) {
                switch (s) {
                    case 0:  stage_w< 52>(sw, wps[0], tid); break;
                    case 1:  stage_w<103>(sw, wps[1], tid); break;
                    case 2:  stage_w<154>(sw, wps[2], tid); break;
                    default: stage_w<256>(sw, wps[3], tid); break;
                }
                cur_s = s;
            }
            __syncthreads();
        }

        int i = pass*NT + tid;
        switch (s) {
            case 0:  if (i < 1160) item1< 52,461>(sx, sw, pps[0], sden, sq, i); break;
            case 1:  if (i < 1040) item1<103,410>(sx, sw, pps[1], sden, sq, i); break;
            case 2:  if (i <  920) item1<154,359>(sx, sw, pps[2], sden, sq, i); break;
            default: if (i <  680) item1<256,257>(sx, sw, pps[3], sden, sq, i); break;
        }
        __syncthreads();              // all items done
        // flush this ticket's partials to global, reset for next ticket
        if (tid < 40) {
            int gi = b*NCOL + s*40 + tid;
            unsigned dv = sden[tid], qv = sq[tid];
            if (dv) atomicMax(&g_d[gi], dv);
            if (qv) atomicMax(&g_q[gi], qv);
            sden[tid] = 0u; sq[tid] = 0u;
        }
        if (tid == 0) sh_t = (int)(atomicAdd(&g_tick, 1u) + NBLK);
        __syncthreads();
        t = sh_t;
        if (t >= NTICK) break;
    }

    // ---- completion counter: last block finalizes ----
    __threadfence();
    __syncthreads();
    if (tid == 0) s_old = atomicAdd(&g_ctr, 1u);
    __syncthreads();
    if (s_old != NBLK - 1) return;

    __threadfence();
    float* sprob = sm;              // [5120]
    float* swout = sm + 5120;       // [1600]
    for (int i = tid; i < NB*NCOL; i += NT) {
        unsigned de = atomicMax(&g_d[i], 0u);   // L2-coherent read
        unsigned qe = atomicMax(&g_q[i], 0u);
        g_d[i] = 0u; g_q[i] = 0u;               // reset for next replay
        float qv = idec(qe);
        float p = expf(-qv*qv);
        out[OFF_DIST + i] = idec(de);
        out[OFF_PROB + i] = p;
        sprob[i] = p;
    }
    for (int i = tid; i < NOUT*NCOL; i += NT) swout[i] = Wout[i];
    __syncthreads();
    for (int tt = tid; tt < NB*NOUT; tt += NT) {
        int bb = tt / NOUT, o = tt - bb*NOUT;
        const float* pr = sprob + bb*NCOL;
        const float* wr = swout + o*NCOL;
        float acc = 0.f;
#pragma unroll 8
        for (int j = 0; j < NCOL; j++) acc += pr[j]*wr[j];
        out[bb*NOUT + o] = acc;
    }
    if (tid == 0) { g_tick = 0u; g_ctr = 0u; }
}

// ---------------- launch ----------------
extern "C" void kernel_launch(void* const* d_in, const int* in_sizes, int n_in,
                              void* d_out, int out_size) {
    const float* x = nullptr;
    const float* w[4] = {nullptr,nullptr,nullptr,nullptr};
    const float* pcm[4] = {nullptr,nullptr,nullptr,nullptr};
    const float* Wout = nullptr;
    for (int i = 0; i < n_in; i++) {
        switch (in_sizes[i]) {
            case 131072: x = (const float*)d_in[i]; break;
            case 2080:  w[0] = (const float*)d_in[i]; break;
            case 4120:  w[1] = (const float*)d_in[i]; break;
            case 6160:  w[2] = (const float*)d_in[i]; break;
            case 10240: w[3] = (const float*)d_in[i]; break;
            case 3688:  pcm[0] = (const float*)d_in[i]; break;
            case 3280:  pcm[1] = (const float*)d_in[i]; break;
            case 2872:  pcm[2] = (const float*)d_in[i]; break;
            case 2056:  pcm[3] = (const float*)d_in[i]; break;
            case 1600:  Wout = (const float*)d_in[i]; break;
            default: break;
        }
    }
    float* out = (float*)d_out;

    cudaFuncSetAttribute(k_all, cudaFuncAttributeMaxDynamicSharedMemorySize, SM_BYTES);

    k_all<<<NBLK, NT, SM_BYTES>>>(x, w[0], w[1], w[2], w[3],
                                  pcm[0], pcm[1], pcm[2], pcm[3], Wout, out);
    (void)out_size;
}